// round 6
// baseline (speedup 1.0000x reference)
#include <cuda_runtime.h>
#include <cuda_bf16.h>
#include <cstdint>

#define NN 8192
#define LEAK 0.7f

// ---------------- global scratch (row-major bf16 hi/lo splits) ------
__device__ __align__(16) __nv_bfloat16 gUh[NN * 64], gUl[NN * 64];     // U[row][k]
__device__ __align__(16) __nv_bfloat16 gVh[NN * 64], gVl[NN * 64];     // V[row][k]
__device__ __align__(16) __nv_bfloat16 gEh[128 * 128 * 64], gEl[128 * 128 * 64]; // [t][dcat][il]

// ---------------- helpers ----------------
__device__ __forceinline__ uint32_t smem_u32(const void* p) {
    uint32_t a;
    asm("{ .reg .u64 t; cvta.to.shared.u64 t, %1; cvt.u32.u64 %0, t; }" : "=r"(a) : "l"(p));
    return a;
}
#define LDSM4(R0, R1, R2, R3, A)                                                 \
    asm volatile("ldmatrix.sync.aligned.m8n8.x4.shared.b16 {%0,%1,%2,%3}, [%4];" \
                 : "=r"(R0), "=r"(R1), "=r"(R2), "=r"(R3) : "r"(A))
#define LDSM4T(R0, R1, R2, R3, A)                                                      \
    asm volatile("ldmatrix.sync.aligned.m8n8.x4.trans.shared.b16 {%0,%1,%2,%3}, [%4];" \
                 : "=r"(R0), "=r"(R1), "=r"(R2), "=r"(R3) : "r"(A))
#define MMA_BF16(c, a0, a1, a2, a3, b0, b1)                                   \
    asm volatile("mma.sync.aligned.m16n8k16.row.col.f32.bf16.bf16.f32 "       \
                 "{%0,%1,%2,%3},{%4,%5,%6,%7},{%8,%9},{%0,%1,%2,%3};"         \
                 : "+f"((c)[0]), "+f"((c)[1]), "+f"((c)[2]), "+f"((c)[3])     \
                 : "r"(a0), "r"(a1), "r"(a2), "r"(a3), "r"(b0), "r"(b1))
#define CP16(dst, src) \
    asm volatile("cp.async.cg.shared.global [%0], [%1], 16;" :: "r"(dst), "l"(src))
#define CP_COMMIT() asm volatile("cp.async.commit_group;" ::: "memory")
#define WG0() asm volatile("cp.async.wait_group 0;" ::: "memory")
#define WG1() asm volatile("cp.async.wait_group 1;" ::: "memory")
#define WG2() asm volatile("cp.async.wait_group 2;" ::: "memory")

__device__ __forceinline__ void split2(float x, __nv_bfloat16& h, __nv_bfloat16& l) {
    h = __float2bfloat16(x);
    l = __float2bfloat16(x - __bfloat162float(h));
}

// ---------------- prep 1: V = U @ W; 16 rows/block, 4 outputs/thread ----------
__global__ void __launch_bounds__(256) prep_embed(const float* __restrict__ U,
                                                  const float* __restrict__ W) {
    __shared__ float Ws[64 * 64];
    __shared__ float Ur[16 * 64];
    int tid = threadIdx.x;
    int row0 = blockIdx.x * 16;
    for (int i = tid; i < 4096; i += 256) Ws[i] = W[i];
    for (int i = tid; i < 1024; i += 256) Ur[i] = U[row0 * 64 + i];
    __syncthreads();
    int rq = tid >> 6, c = tid & 63;
#pragma unroll
    for (int q = 0; q < 4; q++) {
        int r = rq + 4 * q;
        float acc = 0.f;
#pragma unroll 16
        for (int e = 0; e < 64; e++) acc += Ur[r * 64 + e] * Ws[e * 64 + c];
        int row = row0 + r;
        __nv_bfloat16 h, lo;
        split2(Ur[r * 64 + c], h, lo);
        gUh[row * 64 + c] = h;
        gUl[row * 64 + c] = lo;
        split2(acc, h, lo);
        gVh[row * 64 + c] = h;
        gVl[row * 64 + c] = lo;
    }
}

// ---------------- prep 2: eff[t][dcat][il] hi/lo, t = i-chunk of 64 ----------
__global__ void __launch_bounds__(512) prep_eff(const float* __restrict__ S,
                                                const float* __restrict__ prof) {
    __shared__ float es[64 * 129];
    __shared__ float gg[128];
    int t = blockIdx.x, tid = threadIdx.x;
    if (tid < 128) {
        int b = tid >> 6, il = tid & 63;
        float g = prof[b * NN + t * 64 + il] - LEAK;
        gg[tid] = g > 0.f ? g : 0.f;
    }
    __syncthreads();
    for (int idx = tid; idx < 8192; idx += 512) {
        int il = idx >> 7, dc = idx & 127;
        int b = dc >> 6, d = dc & 63;
        es[il * 129 + dc] = S[(b * NN + t * 64 + il) * 64 + d] * gg[b * 64 + il];
    }
    __syncthreads();
    int base = t * 8192;
    for (int idx = tid; idx < 8192; idx += 512) {
        int dc = idx >> 6, il = idx & 63;
        float x = es[il * 129 + dc];
        __nv_bfloat16 h, lo;
        split2(x, h, lo);
        gEh[base + dc * 64 + il] = h;
        gEl[base + dc * 64 + il] = lo;
    }
}

// ---------------- main fused, 1-barrier pipelined mma.sync kernel ----------------
// smem: Vbuf x2 (18432 each: hi 64x144, lo +9216), Ebuf x3 (36864 each: hi 128x144,
// lo +18432), Pbuf x2 (18432 each: hi 64x144, lo +9216). U staged in Pbuf pre-loop.
#define SM_V 0u
#define SM_E 36864u
#define SM_P 147456u
#define SM_TOTAL 184320u

// each warp cp's exactly the V rows (16*mi..+16) and E slice rows (32*nd4..+32)
// that its own ldmatrix reads. Duplicate warps copy identical data (benign race).
__device__ __forceinline__ void cp_self(uint32_t vbuf, uint32_t ebuf, int chunk,
                                        int mi, int nd4, int lane) {
#pragma unroll
    for (int q = 0; q < 8; q++) {
        int lin = q * 32 + lane;
        int h = lin >> 7, rem = lin & 127, r = rem >> 3, c = rem & 7;
        uint32_t dst = vbuf + h * 9216u + (16 * mi + r) * 144u + c * 16u;
        const char* src = (const char*)(h ? gVl : gVh) +
                          ((size_t)(chunk * 64 + 16 * mi + r) * 64 + c * 8) * 2;
        CP16(dst, src);
    }
#pragma unroll
    for (int q = 0; q < 16; q++) {
        int lin = q * 32 + lane;
        int h = lin >> 8, rem = lin & 255, r = rem >> 3, c = rem & 7;
        uint32_t dst = ebuf + h * 18432u + (32 * nd4 + r) * 144u + c * 16u;
        const char* src = (const char*)(h ? gEl : gEh) +
                          ((size_t)chunk * 8192 + (size_t)(32 * nd4 + r) * 64 + c * 8) * 2;
        CP16(dst, src);
    }
}

// GEMM1 (scores) for one chunk + sigmoid epilogue into Pbuf
__device__ __forceinline__ void g1_epi(uint32_t vbuf, uint32_t pbuf, int chunk, int jc,
                                       float bias, const uint32_t ubh[4][8],
                                       const uint32_t ubl[4][8], int mi, int nj,
                                       int lane, int a_r, int a_c) {
    float c1[4][4];
#pragma unroll
    for (int nb = 0; nb < 4; nb++)
#pragma unroll
        for (int q = 0; q < 4; q++) c1[nb][q] = 0.f;

    const uint32_t vh_a = vbuf + (16 * mi + a_r) * 144u + a_c * 2u;
    const uint32_t vl_a = vh_a + 9216u;
#pragma unroll
    for (int ks = 0; ks < 4; ks++) {
        uint32_t ah[4], al[4];
        LDSM4(ah[0], ah[1], ah[2], ah[3], vh_a + ks * 32);
        LDSM4(al[0], al[1], al[2], al[3], vl_a + ks * 32);
#pragma unroll
        for (int nb = 0; nb < 4; nb++) {
            int bi = (nb >> 1) * 4 + (nb & 1) * 2;
            MMA_BF16(c1[nb], ah[0], ah[1], ah[2], ah[3], ubh[ks][bi], ubh[ks][bi + 1]);
            MMA_BF16(c1[nb], ah[0], ah[1], ah[2], ah[3], ubl[ks][bi], ubl[ks][bi + 1]);
            MMA_BF16(c1[nb], al[0], al[1], al[2], al[3], ubh[ks][bi], ubh[ks][bi + 1]);
        }
    }
#pragma unroll
    for (int half = 0; half < 2; half++) {
        int il = 16 * mi + (lane >> 2) + 8 * half;
        int gi = 64 * chunk + il;
        uint32_t rowh = pbuf + il * 144u;
        uint32_t rowl = rowh + 9216u;
#pragma unroll
        for (int nb = 0; nb < 4; nb++) {
            int jl = 32 * nj + 8 * nb + 2 * (lane & 3);
            float x0 = c1[nb][half * 2 + 0] + bias;
            float x1 = c1[nb][half * 2 + 1] + bias;
            float tv0 = __fdividef(1.f, 1.f + __expf(-x0));
            float tv1 = __fdividef(1.f, 1.f + __expf(-x1));
            if (gi == 64 * jc + jl) tv0 = 0.f;
            if (gi == 64 * jc + jl + 1) tv1 = 0.f;
            __nv_bfloat16 h0, l0, h1, l1;
            split2(tv0, h0, l0);
            split2(tv1, h1, l1);
            uint32_t ph = (uint32_t)__bfloat16_as_ushort(h0) |
                          ((uint32_t)__bfloat16_as_ushort(h1) << 16);
            uint32_t pl = (uint32_t)__bfloat16_as_ushort(l0) |
                          ((uint32_t)__bfloat16_as_ushort(l1) << 16);
            asm volatile("st.shared.b32 [%0], %1;" :: "r"(rowh + jl * 2), "r"(ph));
            asm volatile("st.shared.b32 [%0], %1;" :: "r"(rowl + jl * 2), "r"(pl));
        }
    }
}

__global__ void __launch_bounds__(256, 1) dyadic_mma(const float* __restrict__ S,
                                                     const float* __restrict__ bias_p,
                                                     float* __restrict__ out) {
    extern __shared__ char sm[];
    const uint32_t sb = smem_u32(sm);
    const int tid = threadIdx.x, w = tid >> 5, lane = tid & 31;
    const int jc = blockIdx.x;
    const float bias = bias_p[0];

    // ldmatrix lane-address components
    const int a_r = lane & 15;
    const int a_c = (lane & 16) ? 8 : 0;
    const int b_r = (lane & 7) + ((lane & 16) ? 8 : 0);
    const int b_c = (lane & 8) ? 8 : 0;
    const int t_r = (lane & 7) + ((lane & 16) ? 8 : 0);
    const int t_c = ((lane >> 3) & 1) ? 8 : 0;

    // GEMM1 partition: mi (4) x nj (2);  GEMM2 partition: mj2 (2) x nd4 (4)
    const int mi = w & 3, nj = w >> 2;
    const int mj2 = w & 1, nd4 = w >> 1;

    // stage U in Pbuf region
    {
        const uint4* sh = (const uint4*)gUh + jc * 512;
        const uint4* sl = (const uint4*)gUl + jc * 512;
        for (int idx = tid; idx < 512; idx += 256) {
            int r = idx >> 3, c = idx & 7;
            *(uint4*)(sm + SM_P + r * 144 + c * 16) = sh[idx];
            *(uint4*)(sm + SM_P + 9216 + r * 144 + c * 16) = sl[idx];
        }
    }
    cp_self(sb + SM_V, sb + SM_E, 0, mi, nd4, lane); CP_COMMIT();                   // g0
    cp_self(sb + SM_V + 18432u, sb + SM_E + 36864u, 1, mi, nd4, lane); CP_COMMIT(); // g1
    __syncthreads();  // U visible

    // hoist U fragments (loop-invariant GEMM1 B operand)
    uint32_t ubh[4][8], ubl[4][8];
    {
        const uint32_t uh_b = sb + SM_P + (32 * nj + b_r) * 144u + b_c * 2u;
        const uint32_t ul_b = uh_b + 9216u;
#pragma unroll
        for (int ks = 0; ks < 4; ks++)
#pragma unroll
            for (int p = 0; p < 2; p++) {
                LDSM4(ubh[ks][4 * p], ubh[ks][4 * p + 1], ubh[ks][4 * p + 2],
                      ubh[ks][4 * p + 3], uh_b + p * 16 * 144 + ks * 32);
                LDSM4(ubl[ks][4 * p], ubl[ks][4 * p + 1], ubl[ks][4 * p + 2],
                      ubl[ks][4 * p + 3], ul_b + p * 16 * 144 + ks * 32);
            }
    }
    WG1();            // g0 done (own V(0), E(0))
    __syncthreads();  // hoist complete before epi(0) overwrites U staging

    g1_epi(sb + SM_V, sb + SM_P, 0, jc, bias, ubh, ubl, mi, nj, lane, a_r, a_c);

    float d2[2][4][4];
#pragma unroll
    for (int mb = 0; mb < 2; mb++)
#pragma unroll
        for (int nb = 0; nb < 4; nb++)
#pragma unroll
            for (int q = 0; q < 4; q++) d2[mb][nb][q] = 0.f;

    int e3 = 0;            // t % 3
    int e3n = 2;           // (t+2) % 3
    for (int t = 0; t < 128; t++) {
        __syncthreads();   // B1: P(t) visible; all reads of overwrite targets done

        if (t < 126) {
            cp_self(sb + SM_V + (uint32_t)(t & 1) * 18432u,
                    sb + SM_E + (uint32_t)e3n * 36864u, t + 2, mi, nd4, lane);
            CP_COMMIT();
            WG2();         // group t complete -> own E(t) ready
        } else {
            WG0();
        }

        // ---- GEMM2: D2[32j x 32dcat] per warp, K=64, 3-pass, accumulate ----
        {
            const uint32_t pb = sb + SM_P + (uint32_t)(t & 1) * 18432u;
            const uint32_t eb = sb + SM_E + (uint32_t)e3 * 36864u;
            const uint32_t pa0 = pb + t_r * 144u + (32 * mj2 + t_c) * 2u;
            const uint32_t eb0 = eb + (32 * nd4 + b_r) * 144u + b_c * 2u;
#pragma unroll
            for (int ks = 0; ks < 4; ks++) {
                uint32_t ah2[2][4], al2[2][4], bh[8], bl[8];
#pragma unroll
                for (int mb = 0; mb < 2; mb++) {
                    uint32_t pa = pa0 + ks * 16 * 144 + mb * 32;
                    LDSM4T(ah2[mb][0], ah2[mb][1], ah2[mb][2], ah2[mb][3], pa);
                    LDSM4T(al2[mb][0], al2[mb][1], al2[mb][2], al2[mb][3], pa + 9216u);
                }
#pragma unroll
                for (int p = 0; p < 2; p++) {
                    uint32_t ea = eb0 + p * 16 * 144 + ks * 32;
                    LDSM4(bh[4 * p], bh[4 * p + 1], bh[4 * p + 2], bh[4 * p + 3], ea);
                    LDSM4(bl[4 * p], bl[4 * p + 1], bl[4 * p + 2], bl[4 * p + 3],
                          ea + 18432u);
                }
#pragma unroll
                for (int mb = 0; mb < 2; mb++)
#pragma unroll
                    for (int nb = 0; nb < 4; nb++) {
                        int bi = (nb >> 1) * 4 + (nb & 1) * 2;
                        MMA_BF16(d2[mb][nb], ah2[mb][0], ah2[mb][1], ah2[mb][2],
                                 ah2[mb][3], bh[bi], bh[bi + 1]);
                        MMA_BF16(d2[mb][nb], ah2[mb][0], ah2[mb][1], ah2[mb][2],
                                 ah2[mb][3], bl[bi], bl[bi + 1]);
                        MMA_BF16(d2[mb][nb], al2[mb][0], al2[mb][1], al2[mb][2],
                                 al2[mb][3], bh[bi], bh[bi + 1]);
                    }
            }
        }

        // ---- GEMM1(t+1) + epilogue -> Pbuf (t+1)&1 ----
        if (t < 127) {
            if (t < 126) WG1();   // group t+1 complete -> own V(t+1) ready
            g1_epi(sb + SM_V + (uint32_t)((t + 1) & 1) * 18432u,
                   sb + SM_P + (uint32_t)((t + 1) & 1) * 18432u,
                   t + 1, jc, bias, ubh, ubl, mi, nj, lane, a_r, a_c);
        }

        e3 = (e3 == 2) ? 0 : e3 + 1;
        e3n = (e3n == 2) ? 0 : e3n + 1;
    }

    // ---- final: out = S + D2 ----
#pragma unroll
    for (int mb = 0; mb < 2; mb++)
#pragma unroll
        for (int nb = 0; nb < 4; nb++) {
            int dcat = 32 * nd4 + 8 * nb + 2 * (lane & 3);
            int b = dcat >> 6, d = dcat & 63;
#pragma unroll
            for (int half = 0; half < 2; half++) {
                int j = 32 * mj2 + 16 * mb + (lane >> 2) + 8 * half;
                size_t g = ((size_t)(b * NN + 64 * jc + j)) * 64 + d;
                float2 sv = *(const float2*)(S + g);
                float2 ov;
                ov.x = sv.x + d2[mb][nb][half * 2 + 0];
                ov.y = sv.y + d2[mb][nb][half * 2 + 1];
                *(float2*)(out + g) = ov;
            }
        }
}

extern "C" void kernel_launch(void* const* d_in, const int* in_sizes, int n_in,
                              void* d_out, int out_size) {
    const float* S    = (const float*)d_in[0];  // task_states   [2,8192,64]
    const float* prof = (const float*)d_in[1];  // proficiency   [2,8192]
    const float* U    = (const float*)d_in[2];  // task_embeddings [8192,64]
    const float* W    = (const float*)d_in[3];  // bilinear_weight [1,64,64]
    const float* bias = (const float*)d_in[4];  // bilinear_bias  [1]
    float* out = (float*)d_out;

    prep_embed<<<512, 256>>>(U, W);
    prep_eff<<<128, 512>>>(S, prof);

    cudaFuncSetAttribute(dyadic_mma, cudaFuncAttributeMaxDynamicSharedMemorySize, SM_TOTAL);
    dyadic_mma<<<128, 256, SM_TOTAL>>>(S, bias, out);
}

// round 7
// speedup vs baseline: 1.6407x; 1.6407x over previous
#include <cuda_runtime.h>
#include <cuda_bf16.h>
#include <cstdint>

#define NN 8192
#define LEAK 0.7f

// ---------------- global scratch ----------------
__device__ __align__(16) __nv_bfloat16 gUh[NN * 64], gUl[NN * 64];     // U[row][k] full
__device__ __align__(16) __nv_bfloat16 gVh[NN * 64], gVl[NN * 64];     // V[row][k] full
__device__ __align__(16) __nv_bfloat16 gVch[(NN + 64) * 64], gVcl[(NN + 64) * 64]; // compacted V
__device__ __align__(16) __nv_bfloat16 gEh[128 * 128 * 64], gEl[128 * 128 * 64];   // [c][dcat][r]
__device__ int g_idx[NN + 64];
__device__ int g_cnt;

// ---------------- helpers ----------------
__device__ __forceinline__ uint32_t smem_u32(const void* p) {
    uint32_t a;
    asm("{ .reg .u64 t; cvta.to.shared.u64 t, %1; cvt.u32.u64 %0, t; }" : "=r"(a) : "l"(p));
    return a;
}
#define LDSM4(R0, R1, R2, R3, A)                                                 \
    asm volatile("ldmatrix.sync.aligned.m8n8.x4.shared.b16 {%0,%1,%2,%3}, [%4];" \
                 : "=r"(R0), "=r"(R1), "=r"(R2), "=r"(R3) : "r"(A))
#define LDSM4T(R0, R1, R2, R3, A)                                                      \
    asm volatile("ldmatrix.sync.aligned.m8n8.x4.trans.shared.b16 {%0,%1,%2,%3}, [%4];" \
                 : "=r"(R0), "=r"(R1), "=r"(R2), "=r"(R3) : "r"(A))
#define MMA_BF16(c, a0, a1, a2, a3, b0, b1)                                   \
    asm volatile("mma.sync.aligned.m16n8k16.row.col.f32.bf16.bf16.f32 "       \
                 "{%0,%1,%2,%3},{%4,%5,%6,%7},{%8,%9},{%0,%1,%2,%3};"         \
                 : "+f"((c)[0]), "+f"((c)[1]), "+f"((c)[2]), "+f"((c)[3])     \
                 : "r"(a0), "r"(a1), "r"(a2), "r"(a3), "r"(b0), "r"(b1))
#define CP16(dst, src) \
    asm volatile("cp.async.cg.shared.global [%0], [%1], 16;" :: "r"(dst), "l"(src))
#define CP_COMMIT() asm volatile("cp.async.commit_group;" ::: "memory")
#define CP_WAIT0()  asm volatile("cp.async.wait_group 0;" ::: "memory")

__device__ __forceinline__ void split2(float x, __nv_bfloat16& h, __nv_bfloat16& l) {
    h = __float2bfloat16(x);
    l = __float2bfloat16(x - __bfloat162float(h));
}

// ---------------- prep 0: union active-row scan (1 block) ----------------
__global__ void __launch_bounds__(1024) prep_scan(const float* __restrict__ prof) {
    __shared__ int wsum[32];
    int tid = threadIdx.x;
    int base = tid * 8;
    int flags[8], local = 0;
#pragma unroll
    for (int q = 0; q < 8; q++) {
        int i = base + q;
        int a = (prof[i] > LEAK) || (prof[NN + i] > LEAK);
        flags[q] = a;
        local += a;
    }
    int lane = tid & 31, wid = tid >> 5;
    int inc = local;
#pragma unroll
    for (int d = 1; d < 32; d <<= 1) {
        int v = __shfl_up_sync(~0u, inc, d);
        if (lane >= d) inc += v;
    }
    if (lane == 31) wsum[wid] = inc;
    __syncthreads();
    if (wid == 0) {
        int v = wsum[lane];
#pragma unroll
        for (int d = 1; d < 32; d <<= 1) {
            int u = __shfl_up_sync(~0u, v, d);
            if (lane >= d) v += u;
        }
        wsum[lane] = v;
    }
    __syncthreads();
    int excl = inc - local + (wid > 0 ? wsum[wid - 1] : 0);
#pragma unroll
    for (int q = 0; q < 8; q++)
        if (flags[q]) g_idx[excl++] = base + q;
    if (tid == 1023) {
        g_cnt = excl;
        for (int p = excl; p < ((excl + 63) & ~63); p++) g_idx[p] = -1;
    }
}

// ---------------- prep 1: V = U @ W; emit full U,V hi/lo ----------------
__global__ void __launch_bounds__(256) prep_embed(const float* __restrict__ U,
                                                  const float* __restrict__ W) {
    __shared__ float Wt[64 * 68];   // [c][e], stride 68 (17 f4, odd -> conflict-free f4)
    __shared__ float Ur[16 * 64];
    int tid = threadIdx.x;
    int row0 = blockIdx.x * 16;
    for (int i = tid; i < 4096; i += 256) {
        int c = i & 63, e = i >> 6;
        Wt[c * 68 + e] = W[e * 64 + c];
    }
    for (int i = tid; i < 1024; i += 256) Ur[i] = U[row0 * 64 + i];
    __syncthreads();
    int c = tid & 63, rq = tid >> 6;
    float acc[4] = {0.f, 0.f, 0.f, 0.f};
    const float4* wt4 = (const float4*)(Wt + c * 68);
#pragma unroll
    for (int e4 = 0; e4 < 16; e4++) {
        float4 wv = wt4[e4];
#pragma unroll
        for (int q = 0; q < 4; q++) {
            float4 uv = *(const float4*)(Ur + (rq + 4 * q) * 64 + e4 * 4);
            acc[q] += uv.x * wv.x + uv.y * wv.y + uv.z * wv.z + uv.w * wv.w;
        }
    }
#pragma unroll
    for (int q = 0; q < 4; q++) {
        int r = rq + 4 * q, row = row0 + r;
        __nv_bfloat16 h, lo;
        split2(Ur[r * 64 + c], h, lo);
        gUh[row * 64 + c] = h;
        gUl[row * 64 + c] = lo;
        split2(acc[q], h, lo);
        gVh[row * 64 + c] = h;
        gVl[row * 64 + c] = lo;
    }
}

// ---------------- prep 2: compacted V + gated E tiles ----------------
__global__ void __launch_bounds__(256) prep_effV(const float* __restrict__ S,
                                                 const float* __restrict__ prof) {
    int c = blockIdx.x, tid = threadIdx.x;
    int cnt = g_cnt;
    int nt = (cnt + 63) >> 6;
    if (c >= nt) return;
    __shared__ float es[64 * 130];
    __shared__ int sidx[64];
    __shared__ float sg[2][64];
    if (tid < 64) {
        int gi = g_idx[c * 64 + tid];
        sidx[tid] = gi;
        float g0 = 0.f, g1 = 0.f;
        if (gi >= 0) {
            g0 = prof[gi] - LEAK;        g0 = g0 > 0.f ? g0 : 0.f;
            g1 = prof[NN + gi] - LEAK;   g1 = g1 > 0.f ? g1 : 0.f;
        }
        sg[0][tid] = g0;
        sg[1][tid] = g1;
    }
    __syncthreads();
    for (int idx = tid; idx < 8192; idx += 256) {
        int r = idx >> 7, dc = idx & 127;
        int b = dc >> 6, d = dc & 63;
        int gi = sidx[r];
        es[r * 130 + dc] = (gi >= 0) ? S[((size_t)b * NN + gi) * 64 + d] * sg[b][r] : 0.f;
    }
    // compacted V rows (zero-padded)
    for (int idx = tid; idx < 2048; idx += 256) {
        int r = idx >> 5, k2 = idx & 31;
        int gi = sidx[r];
        uint32_t vh = 0u, vl = 0u;
        if (gi >= 0) {
            vh = ((const uint32_t*)gVh)[gi * 32 + k2];
            vl = ((const uint32_t*)gVl)[gi * 32 + k2];
        }
        ((uint32_t*)gVch)[(c * 64 + r) * 32 + k2] = vh;
        ((uint32_t*)gVcl)[(c * 64 + r) * 32 + k2] = vl;
    }
    __syncthreads();
    int base = c * 8192;
    for (int idx = tid; idx < 8192; idx += 256) {
        int dc = idx >> 6, r = idx & 63;
        float x = es[r * 130 + dc];
        __nv_bfloat16 h, lo;
        split2(x, h, lo);
        gEh[base + dc * 64 + r] = h;
        gEl[base + dc * 64 + r] = lo;
    }
}

// ---------------- main fused, double-buffered mma.sync kernel ----------------
#define SM_UH 0u
#define SM_UL 9216u
#define SM_STG 18432u        // stage s: VH+0, VL+9216, EH+18432, EL+36864 (55296 each)
#define STG_SZ 55296u
#define SM_PH 129024u
#define SM_PL 138240u
#define SM_TOTAL 147456u

__device__ __forceinline__ void stage_load(uint32_t stg, int t, int tid) {
#pragma unroll
    for (int idx = tid; idx < 1024; idx += 256) {
        int h = idx >> 9, rem = idx & 511, r = rem >> 3, c = rem & 7;
        uint32_t dst = stg + h * 9216u + r * 144u + c * 16u;
        const char* src = (const char*)(h ? gVcl : gVch) + ((size_t)t * 4096 + r * 64 + c * 8) * 2;
        CP16(dst, src);
    }
#pragma unroll
    for (int idx = tid; idx < 2048; idx += 256) {
        int h = idx >> 10, rem = idx & 1023, r = rem >> 3, c = rem & 7;
        uint32_t dst = stg + 18432u + h * 18432u + r * 144u + c * 16u;
        const char* src = (const char*)(h ? gEl : gEh) + ((size_t)t * 8192 + r * 64 + c * 8) * 2;
        CP16(dst, src);
    }
}

__global__ void __launch_bounds__(256, 1) dyadic_mma(const float* __restrict__ S,
                                                     const float* __restrict__ bias_p,
                                                     float* __restrict__ out) {
    extern __shared__ char sm[];
    const uint32_t sb = smem_u32(sm);
    const int tid = threadIdx.x, w = tid >> 5, lane = tid & 31;
    const int jc = blockIdx.x;
    const float bias = bias_p[0];
    const int nt = (g_cnt + 63) >> 6;

    // resident U tile
    {
        const uint4* sh = (const uint4*)gUh + jc * 512;
        const uint4* sl = (const uint4*)gUl + jc * 512;
        for (int idx = tid; idx < 512; idx += 256) {
            int r = idx >> 3, c = idx & 7;
            *(uint4*)(sm + SM_UH + r * 144 + c * 16) = sh[idx];
            *(uint4*)(sm + SM_UL + r * 144 + c * 16) = sl[idx];
        }
    }

    const int a_r = lane & 15;
    const int a_c = (lane & 16) ? 8 : 0;
    const int b_r = (lane & 7) + ((lane & 16) ? 8 : 0);
    const int b_c = (lane & 8) ? 8 : 0;
    const int t_r = (lane & 7) + ((lane & 16) ? 8 : 0);
    const int t_c = ((lane >> 3) & 1) ? 8 : 0;

    const int mi = w & 3, nj = w >> 2;      // GEMM1 partition
    const int mj = w & 3, nd = w >> 2;      // GEMM2 partition

    float d2[8][4];
#pragma unroll
    for (int nb = 0; nb < 8; nb++)
#pragma unroll
        for (int q = 0; q < 4; q++) d2[nb][q] = 0.f;

    if (nt > 0) {
        stage_load(sb + SM_STG, 0, tid);
        CP_COMMIT();

        const uint32_t uh_b = sb + SM_UH + (32 * nj + b_r) * 144 + b_c * 2;
        const uint32_t ul_b = sb + SM_UL + (32 * nj + b_r) * 144 + b_c * 2;
        const uint32_t ph_a = sb + SM_PH + t_r * 144 + (16 * mj + t_c) * 2;
        const uint32_t pl_a = sb + SM_PL + t_r * 144 + (16 * mj + t_c) * 2;

        __syncthreads();  // U tile visible

        // hoist loop-invariant U fragments
        uint32_t ubh[4][8], ubl[4][8];
#pragma unroll
        for (int ks = 0; ks < 4; ks++)
#pragma unroll
            for (int p = 0; p < 2; p++) {
                LDSM4(ubh[ks][4 * p], ubh[ks][4 * p + 1], ubh[ks][4 * p + 2],
                      ubh[ks][4 * p + 3], uh_b + p * 16 * 144 + ks * 32);
                LDSM4(ubl[ks][4 * p], ubl[ks][4 * p + 1], ubl[ks][4 * p + 2],
                      ubl[ks][4 * p + 3], ul_b + p * 16 * 144 + ks * 32);
            }

        for (int t = 0; t < nt; t++) {
            const int s = t & 1;
            const uint32_t stg = sb + SM_STG + s * STG_SZ;

            CP_WAIT0();
            __syncthreads();  // stage t visible; all warps past GEMM2(t-1)

            if (t + 1 < nt) {
                stage_load(sb + SM_STG + (s ^ 1) * STG_SZ, t + 1, tid);
                CP_COMMIT();
            }

            // ---- GEMM1: C1[16i x 32j] per warp, K=64, 3-pass ----
            float c1[4][4];
#pragma unroll
            for (int nb = 0; nb < 4; nb++)
#pragma unroll
                for (int q = 0; q < 4; q++) c1[nb][q] = 0.f;

            const uint32_t vh_a = stg + (16 * mi + a_r) * 144 + a_c * 2;
            const uint32_t vl_a = stg + 9216u + (16 * mi + a_r) * 144 + a_c * 2;

#pragma unroll
            for (int ks = 0; ks < 4; ks++) {
                uint32_t ah[4], al[4];
                LDSM4(ah[0], ah[1], ah[2], ah[3], vh_a + ks * 32);
                LDSM4(al[0], al[1], al[2], al[3], vl_a + ks * 32);
#pragma unroll
                for (int nb = 0; nb < 4; nb++) {
                    int bi = (nb >> 1) * 4 + (nb & 1) * 2;
                    MMA_BF16(c1[nb], ah[0], ah[1], ah[2], ah[3], ubh[ks][bi], ubh[ks][bi + 1]);
                    MMA_BF16(c1[nb], ah[0], ah[1], ah[2], ah[3], ubl[ks][bi], ubl[ks][bi + 1]);
                    MMA_BF16(c1[nb], al[0], al[1], al[2], al[3], ubh[ks][bi], ubh[ks][bi + 1]);
                }
            }

            // ---- epilogue: sigmoid + idx-based diag mask -> P[il][j] hi/lo ----
            {
#pragma unroll
                for (int half = 0; half < 2; half++) {
                    int il = 16 * mi + (lane >> 2) + 8 * half;
                    int gi = g_idx[64 * t + il];   // global source row (-1 = pad)
                    uint32_t rowh = sb + SM_PH + il * 144;
                    uint32_t rowl = sb + SM_PL + il * 144;
#pragma unroll
                    for (int nb = 0; nb < 4; nb++) {
                        int jl = 32 * nj + 8 * nb + 2 * (lane & 3);
                        float x0 = c1[nb][half * 2 + 0] + bias;
                        float x1 = c1[nb][half * 2 + 1] + bias;
                        float tv0 = __fdividef(1.f, 1.f + __expf(-x0));
                        float tv1 = __fdividef(1.f, 1.f + __expf(-x1));
                        if (gi == 64 * jc + jl) tv0 = 0.f;
                        if (gi == 64 * jc + jl + 1) tv1 = 0.f;
                        __nv_bfloat16 h0, l0, h1, l1;
                        split2(tv0, h0, l0);
                        split2(tv1, h1, l1);
                        uint32_t ph = (uint32_t)__bfloat16_as_ushort(h0) |
                                      ((uint32_t)__bfloat16_as_ushort(h1) << 16);
                        uint32_t pl = (uint32_t)__bfloat16_as_ushort(l0) |
                                      ((uint32_t)__bfloat16_as_ushort(l1) << 16);
                        asm volatile("st.shared.b32 [%0], %1;" :: "r"(rowh + jl * 2), "r"(ph));
                        asm volatile("st.shared.b32 [%0], %1;" :: "r"(rowl + jl * 2), "r"(pl));
                    }
                }
            }
            __syncthreads();  // P visible

            // ---- GEMM2: D2[16j x 64dcat] per warp, K=64, 3-pass, accumulate ----
            const uint32_t eh_b = stg + 18432u + (64 * nd + b_r) * 144 + b_c * 2;
            const uint32_t el_b = stg + 36864u + (64 * nd + b_r) * 144 + b_c * 2;

#pragma unroll
            for (int ks = 0; ks < 4; ks++) {
                uint32_t ah[4], al[4], bh[16], bl[16];
                LDSM4T(ah[0], ah[1], ah[2], ah[3], ph_a + ks * 16 * 144);
                LDSM4T(al[0], al[1], al[2], al[3], pl_a + ks * 16 * 144);
#pragma unroll
                for (int p = 0; p < 4; p++) {
                    LDSM4(bh[4 * p], bh[4 * p + 1], bh[4 * p + 2], bh[4 * p + 3],
                          eh_b + p * 16 * 144 + ks * 32);
                    LDSM4(bl[4 * p], bl[4 * p + 1], bl[4 * p + 2], bl[4 * p + 3],
                          el_b + p * 16 * 144 + ks * 32);
                }
#pragma unroll
                for (int nb = 0; nb < 8; nb++) {
                    int bi = (nb >> 1) * 4 + (nb & 1) * 2;
                    MMA_BF16(d2[nb], ah[0], ah[1], ah[2], ah[3], bh[bi], bh[bi + 1]);
                    MMA_BF16(d2[nb], ah[0], ah[1], ah[2], ah[3], bl[bi], bl[bi + 1]);
                    MMA_BF16(d2[nb], al[0], al[1], al[2], al[3], bh[bi], bh[bi + 1]);
                }
            }
        }
    }

    // ---- final: out = S + D2 ----
    {
        int jrow = 64 * jc + 16 * mj + (lane >> 2);
#pragma unroll
        for (int nb = 0; nb < 8; nb++) {
            int d = 8 * nb + 2 * (lane & 3);
#pragma unroll
            for (int half = 0; half < 2; half++) {
                int j = jrow + half * 8;
                size_t g = ((size_t)(nd * NN + j)) * 64 + d;
                float2 sv = *(const float2*)(S + g);
                float2 ov;
                ov.x = sv.x + d2[nb][half * 2 + 0];
                ov.y = sv.y + d2[nb][half * 2 + 1];
                *(float2*)(out + g) = ov;
            }
        }
    }
}

extern "C" void kernel_launch(void* const* d_in, const int* in_sizes, int n_in,
                              void* d_out, int out_size) {
    const float* S    = (const float*)d_in[0];  // task_states   [2,8192,64]
    const float* prof = (const float*)d_in[1];  // proficiency   [2,8192]
    const float* U    = (const float*)d_in[2];  // task_embeddings [8192,64]
    const float* W    = (const float*)d_in[3];  // bilinear_weight [1,64,64]
    const float* bias = (const float*)d_in[4];  // bilinear_bias  [1]
    float* out = (float*)d_out;

    prep_scan<<<1, 1024>>>(prof);
    prep_embed<<<512, 256>>>(U, W);
    prep_effV<<<128, 256>>>(S, prof);

    cudaFuncSetAttribute(dyadic_mma, cudaFuncAttributeMaxDynamicSharedMemorySize, SM_TOTAL);
    dyadic_mma<<<128, 256, SM_TOTAL>>>(S, bias, out);
}

// round 8
// speedup vs baseline: 1.6421x; 1.0008x over previous
#include <cuda_runtime.h>
#include <cuda_bf16.h>
#include <cstdint>

#define NN 8192
#define LEAK 0.7f

// ---------------- global scratch ----------------
__device__ __align__(16) __nv_bfloat16 gUh[NN * 64], gUl[NN * 64];     // U[row][k] full
__device__ __align__(16) __nv_bfloat16 gVh[NN * 64], gVl[NN * 64];     // V[row][k] full
__device__ __align__(16) __nv_bfloat16 gVch[(NN + 64) * 64], gVcl[(NN + 64) * 64]; // compacted V
__device__ __align__(16) __nv_bfloat16 gEh[128 * 128 * 64], gEl[128 * 128 * 64];   // [c][dcat][r]
__device__ int g_idx[NN + 64];
__device__ int g_cnt;

// ---------------- helpers ----------------
__device__ __forceinline__ uint32_t smem_u32(const void* p) {
    uint32_t a;
    asm("{ .reg .u64 t; cvta.to.shared.u64 t, %1; cvt.u32.u64 %0, t; }" : "=r"(a) : "l"(p));
    return a;
}
#define LDSM4(R0, R1, R2, R3, A)                                                 \
    asm volatile("ldmatrix.sync.aligned.m8n8.x4.shared.b16 {%0,%1,%2,%3}, [%4];" \
                 : "=r"(R0), "=r"(R1), "=r"(R2), "=r"(R3) : "r"(A))
#define LDSM4T(R0, R1, R2, R3, A)                                                      \
    asm volatile("ldmatrix.sync.aligned.m8n8.x4.trans.shared.b16 {%0,%1,%2,%3}, [%4];" \
                 : "=r"(R0), "=r"(R1), "=r"(R2), "=r"(R3) : "r"(A))
#define MMA_BF16(c, a0, a1, a2, a3, b0, b1)                                   \
    asm volatile("mma.sync.aligned.m16n8k16.row.col.f32.bf16.bf16.f32 "       \
                 "{%0,%1,%2,%3},{%4,%5,%6,%7},{%8,%9},{%0,%1,%2,%3};"         \
                 : "+f"((c)[0]), "+f"((c)[1]), "+f"((c)[2]), "+f"((c)[3])     \
                 : "r"(a0), "r"(a1), "r"(a2), "r"(a3), "r"(b0), "r"(b1))
#define CP16(dst, src) \
    asm volatile("cp.async.cg.shared.global [%0], [%1], 16;" :: "r"(dst), "l"(src))
#define CP_COMMIT() asm volatile("cp.async.commit_group;" ::: "memory")
#define CP_WAIT0()  asm volatile("cp.async.wait_group 0;" ::: "memory")

__device__ __forceinline__ void split2(float x, __nv_bfloat16& h, __nv_bfloat16& l) {
    h = __float2bfloat16(x);
    l = __float2bfloat16(x - __bfloat162float(h));
}

// ---------------- prep 0: union active-row scan (1 block) ----------------
__global__ void __launch_bounds__(1024) prep_scan(const float* __restrict__ prof) {
    __shared__ int wsum[32];
    int tid = threadIdx.x;
    int base = tid * 8;
    int flags[8], local = 0;
#pragma unroll
    for (int q = 0; q < 8; q++) {
        int i = base + q;
        int a = (prof[i] > LEAK) || (prof[NN + i] > LEAK);
        flags[q] = a;
        local += a;
    }
    int lane = tid & 31, wid = tid >> 5;
    int inc = local;
#pragma unroll
    for (int d = 1; d < 32; d <<= 1) {
        int v = __shfl_up_sync(~0u, inc, d);
        if (lane >= d) inc += v;
    }
    if (lane == 31) wsum[wid] = inc;
    __syncthreads();
    if (wid == 0) {
        int v = wsum[lane];
#pragma unroll
        for (int d = 1; d < 32; d <<= 1) {
            int u = __shfl_up_sync(~0u, v, d);
            if (lane >= d) v += u;
        }
        wsum[lane] = v;
    }
    __syncthreads();
    int excl = inc - local + (wid > 0 ? wsum[wid - 1] : 0);
#pragma unroll
    for (int q = 0; q < 8; q++)
        if (flags[q]) g_idx[excl++] = base + q;
    if (tid == 1023) {
        g_cnt = excl;
        for (int p = excl; p < ((excl + 63) & ~63); p++) g_idx[p] = -1;
    }
}

// ---------------- prep 1: V = U @ W; emit full U,V hi/lo ----------------
__global__ void __launch_bounds__(256) prep_embed(const float* __restrict__ U,
                                                  const float* __restrict__ W) {
    __shared__ float Wt[64 * 68];
    __shared__ float Ur[16 * 64];
    int tid = threadIdx.x;
    int row0 = blockIdx.x * 16;
    for (int i = tid; i < 4096; i += 256) {
        int c = i & 63, e = i >> 6;
        Wt[c * 68 + e] = W[e * 64 + c];
    }
    for (int i = tid; i < 1024; i += 256) Ur[i] = U[row0 * 64 + i];
    __syncthreads();
    int c = tid & 63, rq = tid >> 6;
    float acc[4] = {0.f, 0.f, 0.f, 0.f};
    const float4* wt4 = (const float4*)(Wt + c * 68);
#pragma unroll
    for (int e4 = 0; e4 < 16; e4++) {
        float4 wv = wt4[e4];
#pragma unroll
        for (int q = 0; q < 4; q++) {
            float4 uv = *(const float4*)(Ur + (rq + 4 * q) * 64 + e4 * 4);
            acc[q] += uv.x * wv.x + uv.y * wv.y + uv.z * wv.z + uv.w * wv.w;
        }
    }
#pragma unroll
    for (int q = 0; q < 4; q++) {
        int r = rq + 4 * q, row = row0 + r;
        __nv_bfloat16 h, lo;
        split2(Ur[r * 64 + c], h, lo);
        gUh[row * 64 + c] = h;
        gUl[row * 64 + c] = lo;
        split2(acc[q], h, lo);
        gVh[row * 64 + c] = h;
        gVl[row * 64 + c] = lo;
    }
}

// ---------------- prep 2: compacted V + gated E tiles ----------------
__global__ void __launch_bounds__(256) prep_effV(const float* __restrict__ S,
                                                 const float* __restrict__ prof) {
    int c = blockIdx.x, tid = threadIdx.x;
    int cnt = g_cnt;
    int nt = (cnt + 63) >> 6;
    if (c >= nt) return;
    __shared__ float es[64 * 130];
    __shared__ int sidx[64];
    __shared__ float sg[2][64];
    if (tid < 64) {
        int gi = g_idx[c * 64 + tid];
        sidx[tid] = gi;
        float g0 = 0.f, g1 = 0.f;
        if (gi >= 0) {
            g0 = prof[gi] - LEAK;        g0 = g0 > 0.f ? g0 : 0.f;
            g1 = prof[NN + gi] - LEAK;   g1 = g1 > 0.f ? g1 : 0.f;
        }
        sg[0][tid] = g0;
        sg[1][tid] = g1;
    }
    __syncthreads();
    for (int idx = tid; idx < 8192; idx += 256) {
        int r = idx >> 7, dc = idx & 127;
        int b = dc >> 6, d = dc & 63;
        int gi = sidx[r];
        es[r * 130 + dc] = (gi >= 0) ? S[((size_t)b * NN + gi) * 64 + d] * sg[b][r] : 0.f;
    }
    for (int idx = tid; idx < 2048; idx += 256) {
        int r = idx >> 5, k2 = idx & 31;
        int gi = sidx[r];
        uint32_t vh = 0u, vl = 0u;
        if (gi >= 0) {
            vh = ((const uint32_t*)gVh)[gi * 32 + k2];
            vl = ((const uint32_t*)gVl)[gi * 32 + k2];
        }
        ((uint32_t*)gVch)[(c * 64 + r) * 32 + k2] = vh;
        ((uint32_t*)gVcl)[(c * 64 + r) * 32 + k2] = vl;
    }
    __syncthreads();
    int base = c * 8192;
    for (int idx = tid; idx < 8192; idx += 256) {
        int dc = idx >> 6, r = idx & 63;
        float x = es[r * 130 + dc];
        __nv_bfloat16 h, lo;
        split2(x, h, lo);
        gEh[base + dc * 64 + r] = h;
        gEl[base + dc * 64 + r] = lo;
    }
}

// ---------------- main fused, double-buffered mma.sync kernel ----------------
#define SM_UH 0u
#define SM_UL 9216u
#define SM_STG 18432u
#define STG_SZ 55296u
#define SM_PH 129024u
#define SM_PL 138240u
#define SM_TOTAL 147456u

__device__ __forceinline__ void stage_load(uint32_t stg, int t, int tid) {
#pragma unroll
    for (int idx = tid; idx < 1024; idx += 256) {
        int h = idx >> 9, rem = idx & 511, r = rem >> 3, c = rem & 7;
        uint32_t dst = stg + h * 9216u + r * 144u + c * 16u;
        const char* src = (const char*)(h ? gVcl : gVch) + ((size_t)t * 4096 + r * 64 + c * 8) * 2;
        CP16(dst, src);
    }
#pragma unroll
    for (int idx = tid; idx < 2048; idx += 256) {
        int h = idx >> 10, rem = idx & 1023, r = rem >> 3, c = rem & 7;
        uint32_t dst = stg + 18432u + h * 18432u + r * 144u + c * 16u;
        const char* src = (const char*)(h ? gEl : gEh) + ((size_t)t * 8192 + r * 64 + c * 8) * 2;
        CP16(dst, src);
    }
}

__global__ void __launch_bounds__(256, 1) dyadic_mma(const float* __restrict__ S,
                                                     const float* __restrict__ bias_p,
                                                     float* __restrict__ out) {
    extern __shared__ char sm[];
    const uint32_t sb = smem_u32(sm);
    const int tid = threadIdx.x, w = tid >> 5, lane = tid & 31;
    const int jc = blockIdx.x;
    const float bias = bias_p[0];
    const int nt = (g_cnt + 63) >> 6;

    // resident U tile
    {
        const uint4* sh = (const uint4*)gUh + jc * 512;
        const uint4* sl = (const uint4*)gUl + jc * 512;
        for (int idx = tid; idx < 512; idx += 256) {
            int r = idx >> 3, c = idx & 7;
            *(uint4*)(sm + SM_UH + r * 144 + c * 16) = sh[idx];
            *(uint4*)(sm + SM_UL + r * 144 + c * 16) = sl[idx];
        }
    }

    const int a_r = lane & 15;
    const int a_c = (lane & 16) ? 8 : 0;
    const int b_r = (lane & 7) + ((lane & 16) ? 8 : 0);
    const int b_c = (lane & 8) ? 8 : 0;
    const int t_r = (lane & 7) + ((lane & 16) ? 8 : 0);
    const int t_c = ((lane >> 3) & 1) ? 8 : 0;

    const int mi = w & 3, nj = w >> 2;      // GEMM1 partition
    const int mj = w & 3, nd = w >> 2;      // GEMM2 partition

    float d2[8][4];
#pragma unroll
    for (int nb = 0; nb < 8; nb++)
#pragma unroll
        for (int q = 0; q < 4; q++) d2[nb][q] = 0.f;

    if (nt > 0) {
        stage_load(sb + SM_STG, 0, tid);
        CP_COMMIT();

        const uint32_t uh_b = sb + SM_UH + (32 * nj + b_r) * 144 + b_c * 2;
        const uint32_t ul_b = sb + SM_UL + (32 * nj + b_r) * 144 + b_c * 2;
        const uint32_t ph_a = sb + SM_PH + t_r * 144 + (16 * mj + t_c) * 2;
        const uint32_t pl_a = sb + SM_PL + t_r * 144 + (16 * mj + t_c) * 2;

        __syncthreads();  // U tile visible

        // hoist loop-invariant U fragments
        uint32_t ubh[4][8], ubl[4][8];
#pragma unroll
        for (int ks = 0; ks < 4; ks++)
#pragma unroll
            for (int p = 0; p < 2; p++) {
                LDSM4(ubh[ks][4 * p], ubh[ks][4 * p + 1], ubh[ks][4 * p + 2],
                      ubh[ks][4 * p + 3], uh_b + p * 16 * 144 + ks * 32);
                LDSM4(ubl[ks][4 * p], ubl[ks][4 * p + 1], ubl[ks][4 * p + 2],
                      ubl[ks][4 * p + 3], ul_b + p * 16 * 144 + ks * 32);
            }

        for (int t = 0; t < nt; t++) {
            const int s = t & 1;
            const uint32_t stg = sb + SM_STG + s * STG_SZ;

            CP_WAIT0();
            __syncthreads();  // stage t visible; all warps past GEMM2(t-1)

            if (t + 1 < nt) {
                stage_load(sb + SM_STG + (s ^ 1) * STG_SZ, t + 1, tid);
                CP_COMMIT();
            }

            // ---- GEMM1: C1[16i x 32j] per warp, K=64, 3-pass, PASS-MAJOR ----
            float c1[4][4];
#pragma unroll
            for (int nb = 0; nb < 4; nb++)
#pragma unroll
                for (int q = 0; q < 4; q++) c1[nb][q] = 0.f;

            const uint32_t vh_a = stg + (16 * mi + a_r) * 144 + a_c * 2;
            const uint32_t vl_a = stg + 9216u + (16 * mi + a_r) * 144 + a_c * 2;

#pragma unroll
            for (int ks = 0; ks < 4; ks++) {
                uint32_t ah[4], al[4];
                LDSM4(ah[0], ah[1], ah[2], ah[3], vh_a + ks * 32);
                LDSM4(al[0], al[1], al[2], al[3], vl_a + ks * 32);
                // pass 0: ah*bh | pass 1: ah*bl | pass 2: al*bh  (per-acc order preserved)
#pragma unroll
                for (int nb = 0; nb < 4; nb++) {
                    int bi = (nb >> 1) * 4 + (nb & 1) * 2;
                    MMA_BF16(c1[nb], ah[0], ah[1], ah[2], ah[3], ubh[ks][bi], ubh[ks][bi + 1]);
                }
#pragma unroll
                for (int nb = 0; nb < 4; nb++) {
                    int bi = (nb >> 1) * 4 + (nb & 1) * 2;
                    MMA_BF16(c1[nb], ah[0], ah[1], ah[2], ah[3], ubl[ks][bi], ubl[ks][bi + 1]);
                }
#pragma unroll
                for (int nb = 0; nb < 4; nb++) {
                    int bi = (nb >> 1) * 4 + (nb & 1) * 2;
                    MMA_BF16(c1[nb], al[0], al[1], al[2], al[3], ubh[ks][bi], ubh[ks][bi + 1]);
                }
            }

            // ---- epilogue: sigmoid + idx-based diag mask -> P[il][j] hi/lo ----
            {
#pragma unroll
                for (int half = 0; half < 2; half++) {
                    int il = 16 * mi + (lane >> 2) + 8 * half;
                    int gi = g_idx[64 * t + il];
                    uint32_t rowh = sb + SM_PH + il * 144;
                    uint32_t rowl = sb + SM_PL + il * 144;
#pragma unroll
                    for (int nb = 0; nb < 4; nb++) {
                        int jl = 32 * nj + 8 * nb + 2 * (lane & 3);
                        float x0 = c1[nb][half * 2 + 0] + bias;
                        float x1 = c1[nb][half * 2 + 1] + bias;
                        float tv0 = __fdividef(1.f, 1.f + __expf(-x0));
                        float tv1 = __fdividef(1.f, 1.f + __expf(-x1));
                        if (gi == 64 * jc + jl) tv0 = 0.f;
                        if (gi == 64 * jc + jl + 1) tv1 = 0.f;
                        __nv_bfloat16 h0, l0, h1, l1;
                        split2(tv0, h0, l0);
                        split2(tv1, h1, l1);
                        uint32_t ph = (uint32_t)__bfloat16_as_ushort(h0) |
                                      ((uint32_t)__bfloat16_as_ushort(h1) << 16);
                        uint32_t pl = (uint32_t)__bfloat16_as_ushort(l0) |
                                      ((uint32_t)__bfloat16_as_ushort(l1) << 16);
                        asm volatile("st.shared.b32 [%0], %1;" :: "r"(rowh + jl * 2), "r"(ph));
                        asm volatile("st.shared.b32 [%0], %1;" :: "r"(rowl + jl * 2), "r"(pl));
                    }
                }
            }
            __syncthreads();  // P visible

            // ---- GEMM2: D2[16j x 64dcat] per warp, K=64, 3-pass, PASS-MAJOR ----
            const uint32_t eh_b = stg + 18432u + (64 * nd + b_r) * 144 + b_c * 2;
            const uint32_t el_b = stg + 36864u + (64 * nd + b_r) * 144 + b_c * 2;

#pragma unroll
            for (int ks = 0; ks < 4; ks++) {
                uint32_t ah[4], al[4], bh[16], bl[16];
                LDSM4T(ah[0], ah[1], ah[2], ah[3], ph_a + ks * 16 * 144);
                LDSM4T(al[0], al[1], al[2], al[3], pl_a + ks * 16 * 144);
#pragma unroll
                for (int p = 0; p < 4; p++) {
                    LDSM4(bh[4 * p], bh[4 * p + 1], bh[4 * p + 2], bh[4 * p + 3],
                          eh_b + p * 16 * 144 + ks * 32);
                    LDSM4(bl[4 * p], bl[4 * p + 1], bl[4 * p + 2], bl[4 * p + 3],
                          el_b + p * 16 * 144 + ks * 32);
                }
#pragma unroll
                for (int nb = 0; nb < 8; nb++) {
                    int bi = (nb >> 1) * 4 + (nb & 1) * 2;
                    MMA_BF16(d2[nb], ah[0], ah[1], ah[2], ah[3], bh[bi], bh[bi + 1]);
                }
#pragma unroll
                for (int nb = 0; nb < 8; nb++) {
                    int bi = (nb >> 1) * 4 + (nb & 1) * 2;
                    MMA_BF16(d2[nb], ah[0], ah[1], ah[2], ah[3], bl[bi], bl[bi + 1]);
                }
#pragma unroll
                for (int nb = 0; nb < 8; nb++) {
                    int bi = (nb >> 1) * 4 + (nb & 1) * 2;
                    MMA_BF16(d2[nb], al[0], al[1], al[2], al[3], bh[bi], bh[bi + 1]);
                }
            }
        }
    }

    // ---- final: out = S + D2 ----
    {
        int jrow = 64 * jc + 16 * mj + (lane >> 2);
#pragma unroll
        for (int nb = 0; nb < 8; nb++) {
            int d = 8 * nb + 2 * (lane & 3);
#pragma unroll
            for (int half = 0; half < 2; half++) {
                int j = jrow + half * 8;
                size_t g = ((size_t)(nd * NN + j)) * 64 + d;
                float2 sv = *(const float2*)(S + g);
                float2 ov;
                ov.x = sv.x + d2[nb][half * 2 + 0];
                ov.y = sv.y + d2[nb][half * 2 + 1];
                *(float2*)(out + g) = ov;
            }
        }
    }
}

extern "C" void kernel_launch(void* const* d_in, const int* in_sizes, int n_in,
                              void* d_out, int out_size) {
    const float* S    = (const float*)d_in[0];  // task_states   [2,8192,64]
    const float* prof = (const float*)d_in[1];  // proficiency   [2,8192]
    const float* U    = (const float*)d_in[2];  // task_embeddings [8192,64]
    const float* W    = (const float*)d_in[3];  // bilinear_weight [1,64,64]
    const float* bias = (const float*)d_in[4];  // bilinear_bias  [1]
    float* out = (float*)d_out;

    prep_scan<<<1, 1024>>>(prof);
    prep_embed<<<512, 256>>>(U, W);
    prep_effV<<<128, 256>>>(S, prof);

    cudaFuncSetAttribute(dyadic_mma, cudaFuncAttributeMaxDynamicSharedMemorySize, SM_TOTAL);
    dyadic_mma<<<128, 256, SM_TOTAL>>>(S, bias, out);
}

// round 9
// speedup vs baseline: 1.9030x; 1.1589x over previous
#include <cuda_runtime.h>
#include <cuda_bf16.h>
#include <cstdint>

#define NN 8192
#define LEAK 0.7f

// ---------------- global scratch ----------------
__device__ __align__(16) __nv_bfloat16 gUh[NN * 64], gUl[NN * 64];
__device__ __align__(16) __nv_bfloat16 gVh[NN * 64], gVl[NN * 64];
__device__ __align__(16) __nv_bfloat16 gVch[(NN + 64) * 64], gVcl[(NN + 64) * 64];
__device__ __align__(16) __nv_bfloat16 gEh[128 * 128 * 64], gEl[128 * 128 * 64]; // [c][dcat][r]
__device__ int g_idx[NN + 64];
__device__ int g_cnt;

// ---------------- helpers ----------------
__device__ __forceinline__ uint32_t smem_u32(const void* p) {
    uint32_t a;
    asm("{ .reg .u64 t; cvta.to.shared.u64 t, %1; cvt.u32.u64 %0, t; }" : "=r"(a) : "l"(p));
    return a;
}
#define LDSM4(R0, R1, R2, R3, A)                                                 \
    asm volatile("ldmatrix.sync.aligned.m8n8.x4.shared.b16 {%0,%1,%2,%3}, [%4];" \
                 : "=r"(R0), "=r"(R1), "=r"(R2), "=r"(R3) : "r"(A))
#define MMA_BF16(c, a0, a1, a2, a3, b0, b1)                                   \
    asm volatile("mma.sync.aligned.m16n8k16.row.col.f32.bf16.bf16.f32 "       \
                 "{%0,%1,%2,%3},{%4,%5,%6,%7},{%8,%9},{%0,%1,%2,%3};"         \
                 : "+f"((c)[0]), "+f"((c)[1]), "+f"((c)[2]), "+f"((c)[3])     \
                 : "r"(a0), "r"(a1), "r"(a2), "r"(a3), "r"(b0), "r"(b1))
#define CP16(dst, src) \
    asm volatile("cp.async.cg.shared.global [%0], [%1], 16;" :: "r"(dst), "l"(src))
#define CP_COMMIT() asm volatile("cp.async.commit_group;" ::: "memory")
#define CP_WAIT0()  asm volatile("cp.async.wait_group 0;" ::: "memory")

__device__ __forceinline__ void split2(float x, __nv_bfloat16& h, __nv_bfloat16& l) {
    h = __float2bfloat16(x);
    l = __float2bfloat16(x - __bfloat162float(h));
}

// ---------------- prep 0: union active-row scan ----------------
__global__ void __launch_bounds__(1024) prep_scan(const float* __restrict__ prof) {
    __shared__ int wsum[32];
    int tid = threadIdx.x;
    int base = tid * 8;
    int flags[8], local = 0;
#pragma unroll
    for (int q = 0; q < 8; q++) {
        int i = base + q;
        int a = (prof[i] > LEAK) || (prof[NN + i] > LEAK);
        flags[q] = a;
        local += a;
    }
    int lane = tid & 31, wid = tid >> 5;
    int inc = local;
#pragma unroll
    for (int d = 1; d < 32; d <<= 1) {
        int v = __shfl_up_sync(~0u, inc, d);
        if (lane >= d) inc += v;
    }
    if (lane == 31) wsum[wid] = inc;
    __syncthreads();
    if (wid == 0) {
        int v = wsum[lane];
#pragma unroll
        for (int d = 1; d < 32; d <<= 1) {
            int u = __shfl_up_sync(~0u, v, d);
            if (lane >= d) v += u;
        }
        wsum[lane] = v;
    }
    __syncthreads();
    int excl = inc - local + (wid > 0 ? wsum[wid - 1] : 0);
#pragma unroll
    for (int q = 0; q < 8; q++)
        if (flags[q]) g_idx[excl++] = base + q;
    if (tid == 1023) {
        g_cnt = excl;
        for (int p = excl; p < ((excl + 63) & ~63); p++) g_idx[p] = -1;
    }
}

// ---------------- prep 1: V = U @ W ----------------
__global__ void __launch_bounds__(256) prep_embed(const float* __restrict__ U,
                                                  const float* __restrict__ W) {
    __shared__ float Wt[64 * 68];
    __shared__ float Ur[16 * 64];
    int tid = threadIdx.x;
    int row0 = blockIdx.x * 16;
    for (int i = tid; i < 4096; i += 256) {
        int c = i & 63, e = i >> 6;
        Wt[c * 68 + e] = W[e * 64 + c];
    }
    for (int i = tid; i < 1024; i += 256) Ur[i] = U[row0 * 64 + i];
    __syncthreads();
    int c = tid & 63, rq = tid >> 6;
    float acc[4] = {0.f, 0.f, 0.f, 0.f};
    const float4* wt4 = (const float4*)(Wt + c * 68);
#pragma unroll
    for (int e4 = 0; e4 < 16; e4++) {
        float4 wv = wt4[e4];
#pragma unroll
        for (int q = 0; q < 4; q++) {
            float4 uv = *(const float4*)(Ur + (rq + 4 * q) * 64 + e4 * 4);
            acc[q] += uv.x * wv.x + uv.y * wv.y + uv.z * wv.z + uv.w * wv.w;
        }
    }
#pragma unroll
    for (int q = 0; q < 4; q++) {
        int r = rq + 4 * q, row = row0 + r;
        __nv_bfloat16 h, lo;
        split2(Ur[r * 64 + c], h, lo);
        gUh[row * 64 + c] = h;
        gUl[row * 64 + c] = lo;
        split2(acc[q], h, lo);
        gVh[row * 64 + c] = h;
        gVl[row * 64 + c] = lo;
    }
}

// ---------------- prep 2: compacted V + gated E tiles ----------------
__global__ void __launch_bounds__(256) prep_effV(const float* __restrict__ S,
                                                 const float* __restrict__ prof) {
    int c = blockIdx.x, tid = threadIdx.x;
    int cnt = g_cnt;
    int nt = (cnt + 63) >> 6;
    if (c >= nt) return;
    __shared__ float es[64 * 130];
    __shared__ int sidx[64];
    __shared__ float sg[2][64];
    if (tid < 64) {
        int gi = g_idx[c * 64 + tid];
        sidx[tid] = gi;
        float g0 = 0.f, g1 = 0.f;
        if (gi >= 0) {
            g0 = prof[gi] - LEAK;        g0 = g0 > 0.f ? g0 : 0.f;
            g1 = prof[NN + gi] - LEAK;   g1 = g1 > 0.f ? g1 : 0.f;
        }
        sg[0][tid] = g0;
        sg[1][tid] = g1;
    }
    __syncthreads();
    for (int idx = tid; idx < 8192; idx += 256) {
        int r = idx >> 7, dc = idx & 127;
        int b = dc >> 6, d = dc & 63;
        int gi = sidx[r];
        es[r * 130 + dc] = (gi >= 0) ? S[((size_t)b * NN + gi) * 64 + d] * sg[b][r] : 0.f;
    }
    for (int idx = tid; idx < 2048; idx += 256) {
        int r = idx >> 5, k2 = idx & 31;
        int gi = sidx[r];
        uint32_t vh = 0u, vl = 0u;
        if (gi >= 0) {
            vh = ((const uint32_t*)gVh)[gi * 32 + k2];
            vl = ((const uint32_t*)gVl)[gi * 32 + k2];
        }
        ((uint32_t*)gVch)[(c * 64 + r) * 32 + k2] = vh;
        ((uint32_t*)gVcl)[(c * 64 + r) * 32 + k2] = vl;
    }
    __syncthreads();
    int base = c * 8192;
    for (int idx = tid; idx < 8192; idx += 256) {
        int dc = idx >> 6, r = idx & 63;
        float x = es[r * 130 + dc];
        __nv_bfloat16 h, lo;
        split2(x, h, lo);
        gEh[base + dc * 64 + r] = h;
        gEl[base + dc * 64 + r] = lo;
    }
}

// ---------------- main: fragment-reuse (no P smem), 1 barrier/iter ----------------
#define SM_U 0u
#define SM_STG 18432u
#define STG_SZ 55552u   // V(18432) + E(36864) + idx(256)
#define SM_TOTAL (18432u + 2u * 55552u)   // 129536

__device__ __forceinline__ void stage_load(uint32_t stg, int t, int tid) {
#pragma unroll
    for (int idx = tid; idx < 1024; idx += 256) {
        int h = idx >> 9, rem = idx & 511, r = rem >> 3, c = rem & 7;
        uint32_t dst = stg + h * 9216u + r * 144u + c * 16u;
        const char* src = (const char*)(h ? gVcl : gVch) + ((size_t)t * 4096 + r * 64 + c * 8) * 2;
        CP16(dst, src);
    }
#pragma unroll
    for (int idx = tid; idx < 2048; idx += 256) {
        int h = idx >> 10, rem = idx & 1023, r = rem >> 3, c = rem & 7;
        uint32_t dst = stg + 18432u + h * 18432u + r * 144u + c * 16u;
        const char* src = (const char*)(h ? gEl : gEh) + ((size_t)t * 8192 + r * 64 + c * 8) * 2;
        CP16(dst, src);
    }
    if (tid < 16)
        CP16(stg + 55296u + tid * 16u, (const char*)(g_idx + t * 64) + tid * 16);
}

__global__ void __launch_bounds__(256, 1) dyadic_mma(const float* __restrict__ S,
                                                     const float* __restrict__ bias_p,
                                                     float* __restrict__ out) {
    extern __shared__ char sm[];
    const uint32_t sb = smem_u32(sm);
    const int tid = threadIdx.x, w = tid >> 5, lane = tid & 31;
    const int jc = blockIdx.x;
    const float bias = bias_p[0];
    const int nt = (g_cnt + 63) >> 6;

    const int g = lane >> 2, tig = lane & 3;
    const int a_r = lane & 15;
    const int a_c = (lane & 16) ? 8 : 0;
    const int b_r = (lane & 7) + ((lane & 16) ? 8 : 0);
    const int b_c = (lane & 8) ? 8 : 0;

    const int mj = w & 3;   // j slice: [16*mj, +16)
    const int nw = w >> 2;  // i slice: [32*nw, +32) (K split for GEMM2)

    // stage resident U tile
    {
        const uint4* sh = (const uint4*)gUh + jc * 512;
        const uint4* sl = (const uint4*)gUl + jc * 512;
        for (int idx = tid; idx < 512; idx += 256) {
            int r = idx >> 3, c = idx & 7;
            *(uint4*)(sm + SM_U + r * 144 + c * 16) = sh[idx];
            *(uint4*)(sm + SM_U + 9216 + r * 144 + c * 16) = sl[idx];
        }
    }
    stage_load(sb + SM_STG, 0, tid);
    CP_COMMIT();

    float d2[16][4];
#pragma unroll
    for (int nb = 0; nb < 16; nb++)
#pragma unroll
        for (int q = 0; q < 4; q++) d2[nb][q] = 0.f;

    __syncthreads();  // U visible

    // hoist A = U rows [16*mj, +16): loop-invariant GEMM1 A operand
    uint32_t uah[4][4], ual[4][4];
    {
        const uint32_t ua = sb + SM_U + (16 * mj + a_r) * 144 + a_c * 2;
#pragma unroll
        for (int ks = 0; ks < 4; ks++) {
            LDSM4(uah[ks][0], uah[ks][1], uah[ks][2], uah[ks][3], ua + ks * 32);
            LDSM4(ual[ks][0], ual[ks][1], ual[ks][2], ual[ks][3], ua + 9216u + ks * 32);
        }
    }

    for (int t = 0; t < nt; t++) {
        const uint32_t stg = sb + SM_STG + (uint32_t)(t & 1) * STG_SZ;

        CP_WAIT0();
        __syncthreads();  // stage t visible; prior iter's reads of the other buffer done

        if (t + 1 < nt) {
            stage_load(sb + SM_STG + (uint32_t)((t + 1) & 1) * STG_SZ, t + 1, tid);
            CP_COMMIT();
        }

        // ---- GEMM1: C[16j x 32i], A = hoisted U, B = V rows [32*nw, +32), 3-pass ----
        float c1[4][4];
#pragma unroll
        for (int nb = 0; nb < 4; nb++)
#pragma unroll
            for (int q = 0; q < 4; q++) c1[nb][q] = 0.f;

        const uint32_t vbh_base = stg + (32 * nw + b_r) * 144 + b_c * 2;
        const uint32_t vbl_base = vbh_base + 9216u;
#pragma unroll
        for (int ks = 0; ks < 4; ks++) {
            uint32_t bh[8], bl[8];
#pragma unroll
            for (int p = 0; p < 2; p++) {
                LDSM4(bh[4 * p], bh[4 * p + 1], bh[4 * p + 2], bh[4 * p + 3],
                      vbh_base + p * 16 * 144 + ks * 32);
                LDSM4(bl[4 * p], bl[4 * p + 1], bl[4 * p + 2], bl[4 * p + 3],
                      vbl_base + p * 16 * 144 + ks * 32);
            }
#pragma unroll
            for (int nb = 0; nb < 4; nb++) {
                int bi = (nb >> 1) * 4 + (nb & 1) * 2;
                MMA_BF16(c1[nb], uah[ks][0], uah[ks][1], uah[ks][2], uah[ks][3],
                         bh[bi], bh[bi + 1]);
            }
#pragma unroll
            for (int nb = 0; nb < 4; nb++) {
                int bi = (nb >> 1) * 4 + (nb & 1) * 2;
                MMA_BF16(c1[nb], uah[ks][0], uah[ks][1], uah[ks][2], uah[ks][3],
                         bl[bi], bl[bi + 1]);
            }
#pragma unroll
            for (int nb = 0; nb < 4; nb++) {
                int bi = (nb >> 1) * 4 + (nb & 1) * 2;
                MMA_BF16(c1[nb], ual[ks][0], ual[ks][1], ual[ks][2], ual[ks][3],
                         bh[bi], bh[bi + 1]);
            }
        }

        // ---- epilogue IN REGISTERS: sigmoid + mask + hi/lo split + A-frag pack ----
        uint32_t pah[2][4], pal[2][4];
#pragma unroll
        for (int nb = 0; nb < 4; nb++) {
            uint32_t i0, i1;
            asm volatile("ld.shared.v2.u32 {%0,%1}, [%2];" : "=r"(i0), "=r"(i1)
                         : "r"(stg + 55296u + (uint32_t)(32 * nw + 8 * nb + 2 * tig) * 4u));
            float tv[4];
#pragma unroll
            for (int q = 0; q < 4; q++) {
                float x = c1[nb][q] + bias;
                float s = __fdividef(1.f, 1.f + __expf(-x));
                int gi = (int)((q & 1) ? i1 : i0);
                int jg = 64 * jc + 16 * mj + g + ((q & 2) ? 8 : 0);
                if (gi == jg) s = 0.f;
                tv[q] = s;
            }
            __nv_bfloat16 h0, l0, h1, l1, h2, l2, h3, l3;
            split2(tv[0], h0, l0);
            split2(tv[1], h1, l1);
            split2(tv[2], h2, l2);
            split2(tv[3], h3, l3);
            int ks2 = nb >> 1, ai = 2 * (nb & 1);
            pah[ks2][ai]     = (uint32_t)__bfloat16_as_ushort(h0) |
                               ((uint32_t)__bfloat16_as_ushort(h1) << 16);
            pah[ks2][ai + 1] = (uint32_t)__bfloat16_as_ushort(h2) |
                               ((uint32_t)__bfloat16_as_ushort(h3) << 16);
            pal[ks2][ai]     = (uint32_t)__bfloat16_as_ushort(l0) |
                               ((uint32_t)__bfloat16_as_ushort(l1) << 16);
            pal[ks2][ai + 1] = (uint32_t)__bfloat16_as_ushort(l2) |
                               ((uint32_t)__bfloat16_as_ushort(l3) << 16);
        }

        // ---- GEMM2: D2[16j x 128dcat] += P^T . E, K = this warp's 32 i, 3-pass ----
        const uint32_t eb_base = stg + 18432u + b_r * 144u + b_c * 2u + (uint32_t)(64 * nw);
#pragma unroll
        for (int ks2 = 0; ks2 < 2; ks2++) {
#pragma unroll
            for (int p = 0; p < 8; p++) {
                uint32_t bh[4], bl[4];
                uint32_t ea = eb_base + p * 16 * 144 + ks2 * 32;
                LDSM4(bh[0], bh[1], bh[2], bh[3], ea);
                LDSM4(bl[0], bl[1], bl[2], bl[3], ea + 18432u);
#pragma unroll
                for (int blk = 0; blk < 2; blk++) {
                    int nb = 2 * p + blk;
                    MMA_BF16(d2[nb], pah[ks2][0], pah[ks2][1], pah[ks2][2], pah[ks2][3],
                             bh[2 * blk], bh[2 * blk + 1]);
                    MMA_BF16(d2[nb], pah[ks2][0], pah[ks2][1], pah[ks2][2], pah[ks2][3],
                             bl[2 * blk], bl[2 * blk + 1]);
                    MMA_BF16(d2[nb], pal[ks2][0], pal[ks2][1], pal[ks2][2], pal[ks2][3],
                             bh[2 * blk], bh[2 * blk + 1]);
                }
            }
        }
    }

    // ---- cross-warp K reduction (nw pairs) + epilogue store ----
    __syncthreads();
    float* red = (float*)(sm + SM_STG);
    if (nw == 1) {
#pragma unroll
        for (int nb = 0; nb < 16; nb++)
#pragma unroll
            for (int q = 0; q < 4; q++)
                red[(mj * 64 + nb * 4 + q) * 32 + lane] = d2[nb][q];
    }
    __syncthreads();
    if (nw == 0) {
#pragma unroll
        for (int nb = 0; nb < 16; nb++)
#pragma unroll
            for (int q = 0; q < 4; q++)
                d2[nb][q] += red[(mj * 64 + nb * 4 + q) * 32 + lane];
#pragma unroll
        for (int nb = 0; nb < 16; nb++) {
            int b = nb >> 3, d = 8 * (nb & 7) + 2 * tig;
#pragma unroll
            for (int half = 0; half < 2; half++) {
                int j = 64 * jc + 16 * mj + g + 8 * half;
                size_t off = ((size_t)(b * NN + j)) * 64 + d;
                float2 sv = *(const float2*)(S + off);
                float2 ov;
                ov.x = sv.x + d2[nb][2 * half + 0];
                ov.y = sv.y + d2[nb][2 * half + 1];
                *(float2*)(out + off) = ov;
            }
        }
    }
}

extern "C" void kernel_launch(void* const* d_in, const int* in_sizes, int n_in,
                              void* d_out, int out_size) {
    const float* S    = (const float*)d_in[0];  // task_states   [2,8192,64]
    const float* prof = (const float*)d_in[1];  // proficiency   [2,8192]
    const float* U    = (const float*)d_in[2];  // task_embeddings [8192,64]
    const float* W    = (const float*)d_in[3];  // bilinear_weight [1,64,64]
    const float* bias = (const float*)d_in[4];  // bilinear_bias  [1]
    float* out = (float*)d_out;

    prep_scan<<<1, 1024>>>(prof);
    prep_embed<<<512, 256>>>(U, W);
    prep_effV<<<128, 256>>>(S, prof);

    cudaFuncSetAttribute(dyadic_mma, cudaFuncAttributeMaxDynamicSharedMemorySize, SM_TOTAL);
    dyadic_mma<<<128, 256, SM_TOTAL>>>(S, bias, out);
}